// round 17
// baseline (speedup 1.0000x reference)
#include <cuda_runtime.h>

#define NB 16
#define NS 4
#define NK 11
#define NBS (NB * NS)         // 64
#define NBSK (NB * NS * NK)   // 704
#define NTHR 128

// Scratch: per-(b,s,k) partials + per-(b,s) arrival counters. Static device
// globals (no allocation). Counters zero at load; finisher resets them each
// launch so graph replays stay deterministic.
__device__ float    g_part[2 * NBSK];
__device__ unsigned g_cnt[NBS];

// RELEASE-only atomic: orders prior .cg stores; no acquire half -> no
// CCTL.IVALL (L1 invalidate). Reader uses ld.cg so no acquire needed.
__device__ __forceinline__ unsigned atom_add_release_gpu(unsigned* p, unsigned v)
{
    unsigned old;
    asm volatile("atom.release.gpu.global.add.u32 %0, [%1], %2;"
                 : "=r"(old) : "l"(p), "r"(v) : "memory");
    return old;
}

// 128 threads, 6 CTAs/SM resident (24 warps/SM): 704 CTAs in ONE wave with
// +20% outstanding loads per SM vs the 5-CTA variant. Regs capped at 85 —
// batch-4 body (8 float4 buffers) still fits without spills.
__global__ void __launch_bounds__(NTHR, 6)
keypoint_main_kernel(const float* __restrict__ cp,     // (16,4,22,128,128)
                     const float* __restrict__ heat,   // (16,11,128,128)
                     const float* __restrict__ lab,    // (16,11,11)
                     float* __restrict__ out)          // 128 floats
{
    const int bsk = blockIdx.x;          // 0..703
    const int k   = bsk % NK;
    const int bs  = bsk / NK;            // b*4+s
    const int b   = bs >> 2;

    const float4* __restrict__ hptr =
        (const float4*)(cp + ((size_t)(bs * 22 + k) << 14));
    const float4* __restrict__ gptr =
        (const float4*)(heat + ((size_t)(b * NK + k) << 14));

    const int t = threadIdx.x;           // 0..127

    float s0 = 0.0f, s1 = 0.0f;
    float mx = -__int_as_float(0x7f800000); // -inf
    int   mi = 0;

    // 4096 float4/map / 128 thr = 32 f4 per thread per stream.
    // Batches of 4: 8 LDG.128 in flight per thread (R8's proven pattern).
    // hm is single-use -> __ldcs (evict-first) preserves L2 for the
    // 4x-reused heatmaps; g uses the default policy.
    #pragma unroll
    for (int j = 0; j < 8; j++) {
        float4 h[4], g[4];
        #pragma unroll
        for (int u = 0; u < 4; u++) {
            const int v = t + (j * 4 + u) * NTHR;   // [0,4096)
            h[u] = __ldcs(&hptr[v]);
            g[u] = gptr[v];
        }
        #pragma unroll
        for (int u = 0; u < 4; u++) {
            const int v = t + (j * 4 + u) * NTHR;
            float d0 = h[u].x - g[u].x, d1 = h[u].y - g[u].y;
            float d2 = h[u].z - g[u].z, d3 = h[u].w - g[u].w;
            s0 = fmaf(d0, d0, s0);
            s1 = fmaf(d1, d1, s1);
            s0 = fmaf(d2, d2, s0);
            s1 = fmaf(d3, d3, s1);
            const int base = v << 2;
            // ascending index within thread -> strict > = first occurrence
            if (h[u].x > mx) { mx = h[u].x; mi = base; }
            if (h[u].y > mx) { mx = h[u].y; mi = base + 1; }
            if (h[u].z > mx) { mx = h[u].z; mi = base + 2; }
            if (h[u].w > mx) { mx = h[u].w; mi = base + 3; }
        }
    }
    float sum = s0 + s1;

    // Warp reduce (sum, argmax with lowest-index tiebreak)
    #pragma unroll
    for (int off = 16; off > 0; off >>= 1) {
        float osum = __shfl_down_sync(0xffffffffu, sum, off);
        float omx  = __shfl_down_sync(0xffffffffu, mx,  off);
        int   omi  = __shfl_down_sync(0xffffffffu, mi,  off);
        sum += osum;
        if (omx > mx || (omx == mx && omi < mi)) { mx = omx; mi = omi; }
    }

    __shared__ float ssum[4];
    __shared__ float smx[4];
    __shared__ int   smi[4];
    const int w = t >> 5, l = t & 31;
    if (l == 0) { ssum[w] = sum; smx[w] = mx; smi[w] = mi; }
    __syncthreads();

    if (t == 0) {
        #pragma unroll
        for (int w2 = 1; w2 < 4; w2++) {
            sum += ssum[w2];
            if (smx[w2] > mx || (smx[w2] == mx && smi[w2] < mi)) {
                mx = smx[w2]; mi = smi[w2];
            }
        }

        // ---- label-loss term for this (b,s,k) ----
        const float* __restrict__ lp =
            cp + ((size_t)(bs * 22 + NK + k) << 14);     // lb map, first 9 used
        const float* __restrict__ lb = lab + (size_t)(b * NK + k) * 11;

        const float gx = lb[9];
        const float gy = lb[10];
        const bool valid = (gx > 0.0f) && (gy > 0.0f) &&
                           (gx < 128.0f) && (gy < 128.0f);

        const float xf = (float)(mi >> 7);    // index // 128
        const float yf = (float)(mi & 127);   // index % 128

        const float dx = gx + lb[7] - xf - lp[7];
        const float dy = gy + lb[8] - yf - lp[8];
        const float xy_loss = dx * dx + dy * dy;

        const float c = 1.0f - mx;
        const float conf_loss = c * c;

        float cls = 0.0f;
        #pragma unroll
        for (int j = 0; j < 7; j++) {
            const float d = lp[j] - lb[j];
            cls = fmaf(d, d, cls);
        }

        // L1-bypass stores: land in L2, visible to any finisher on any SM.
        __stcg(&g_part[bsk], sum);
        __stcg(&g_part[NBSK + bsk],
               valid ? (cls + xy_loss + conf_loss) : 0.0f);

        // Release-only ordering; reader uses ld.cg (L1-bypass).
        const unsigned prev = atom_add_release_gpu(&g_cnt[bs], 1u);
        if (prev == NK - 1) {
            g_cnt[bs] = 0;               // reset for next graph replay
            float hsum = 0.0f, lsum = 0.0f;
            #pragma unroll
            for (int kk = 0; kk < NK; kk++) {
                hsum += __ldcg(&g_part[bs * NK + kk]);
                lsum += __ldcg(&g_part[NBSK + bs * NK + kk]);
            }
            out[bs]      = hsum;         // heat_loss (16,4)
            out[64 + bs] = lsum;         // label_loss (16,4)
        }
    }
}

extern "C" void kernel_launch(void* const* d_in, const int* in_sizes, int n_in,
                              void* d_out, int out_size)
{
    const float* cp   = (const float*)d_in[0]; // combined_preds
    const float* heat = (const float*)d_in[1]; // heatmaps
    const float* lab  = (const float*)d_in[2]; // labels
    float* out = (float*)d_out;

    keypoint_main_kernel<<<NBSK, NTHR>>>(cp, heat, lab, out);
}